// round 7
// baseline (speedup 1.0000x reference)
#include <cuda_runtime.h>

// Problem constants
#define NB 4
#define NN 4096
#define NC 128
#define NKCH 3                       // Chebyshev K
#define LRF ((float)(2.0 / (2.0 + 1e-6)))   // lambda_ratio

// Scratch: Z = [b][k][n][c] contiguous per batch => the torch .view(B,N,-1)
// of stacked [B,K,N,C] is exactly rows of stride 384 over this buffer.
__device__ float g_Z[(size_t)NB * NKCH * NN * NC];     // 24 MB
__device__ float g_degpart[16 * NB * NN];              // 1 MB, deterministic 2-stage
__device__ float g_deg[NB * NN];

// ---------------------------------------------------------------------------
// degree[b,n] = sum_m adj[b,m,n]  (column sums), deterministic 2-stage
// ---------------------------------------------------------------------------
__global__ void degree_partial_kernel(const float* __restrict__ adj) {
    // grid: (NN/128, 16, NB), block 128
    const int b   = blockIdx.z;
    const int col = blockIdx.x * 128 + threadIdx.x;
    const int r0  = blockIdx.y * 256;
    const float* A = adj + (size_t)b * NN * NN;
    float s = 0.f;
#pragma unroll 8
    for (int m = 0; m < 256; ++m)
        s += A[(size_t)(r0 + m) * NN + col];
    g_degpart[(size_t)blockIdx.y * NB * NN + b * NN + col] = s;
}

__global__ void degree_reduce_kernel() {
    int i = blockIdx.x * blockDim.x + threadIdx.x;
    if (i < NB * NN) {
        float s = 0.f;
#pragma unroll
        for (int r = 0; r < 16; ++r)
            s += g_degpart[(size_t)r * NB * NN + i];
        g_deg[i] = s;
    }
}

// ---------------------------------------------------------------------------
// Fused Chebyshev step GEMM:
//   acc[n,c] = sum_m adj[b,n,m] * Zin[b,m,c]
//   Zout[n,c] = alpha*( LR*(deg[n]*Zin[n,c] - acc) - Zin[n,c] ) + beta*x[n,c]
// step1: Zin=x    (zin_slice=-1), zout=1, alpha=1, beta=0, copy_x=1 (fills slice 0)
// step2: Zin=T1   (zin_slice= 1), zout=2, alpha=2, beta=-1
//
// 128x128x8 tiled SGEMM, 256 threads, 8x8 per thread, split-quadrant smem
// reads (conflict-free LDS.128), register prefetch of next tiles.
// ---------------------------------------------------------------------------
__global__ __launch_bounds__(256, 1)
void cheb_gemm_kernel(const float* __restrict__ adj,
                      const float* __restrict__ x,
                      int zin_slice, int zout_slice,
                      float alpha, float beta, int copy_x)
{
    const int b    = blockIdx.y;
    const int row0 = blockIdx.x * 128;

    const float* A  = adj + (size_t)b * NN * NN + (size_t)row0 * NN;
    const float* Zb = (zin_slice < 0)
        ? (x + (size_t)b * NN * NC)
        : (g_Z + ((size_t)b * NKCH + zin_slice) * NN * NC);
    float* Zo  = g_Z + ((size_t)b * NKCH + zout_slice) * NN * NC;
    float* Zo0 = g_Z + ((size_t)b * NKCH + 0) * NN * NC;

    __shared__ float As[8][128];   // [k][row]
    __shared__ float Bs[8][128];   // [k][col]

    const int tid  = threadIdx.x;
    const int tx   = tid & 15;     // col group
    const int ty   = tid >> 4;     // row group
    const int aRow = tid >> 1;             // 0..127
    const int aCol = (tid & 1) << 2;       // 0 or 4
    const int bRow = tid >> 5;             // 0..7
    const int bCol = (tid & 31) << 2;      // 0..124

    float acc[8][8];
#pragma unroll
    for (int i = 0; i < 8; ++i)
#pragma unroll
        for (int j = 0; j < 8; ++j) acc[i][j] = 0.f;

    // prefetch first tiles
    float4 av = *(const float4*)(A + (size_t)aRow * NN + aCol);
    float4 bv = *(const float4*)(Zb + (size_t)bRow * NC + bCol);

    for (int k0 = 0; k0 < NN; k0 += 8) {
        // commit prefetched tiles to smem (As stored k-major = transposed)
        As[aCol + 0][aRow] = av.x;
        As[aCol + 1][aRow] = av.y;
        As[aCol + 2][aRow] = av.z;
        As[aCol + 3][aRow] = av.w;
        *(float4*)&Bs[bRow][bCol] = bv;
        __syncthreads();

        if (k0 + 8 < NN) {
            av = *(const float4*)(A + (size_t)aRow * NN + (k0 + 8) + aCol);
            bv = *(const float4*)(Zb + (size_t)(k0 + 8 + bRow) * NC + bCol);
        }

#pragma unroll
        for (int kk = 0; kk < 8; ++kk) {
            float a[8], bb[8];
            *(float4*)&a[0]  = *(const float4*)&As[kk][ty * 4];
            *(float4*)&a[4]  = *(const float4*)&As[kk][64 + ty * 4];
            *(float4*)&bb[0] = *(const float4*)&Bs[kk][tx * 4];
            *(float4*)&bb[4] = *(const float4*)&Bs[kk][64 + tx * 4];
#pragma unroll
            for (int i = 0; i < 8; ++i)
#pragma unroll
                for (int j = 0; j < 8; ++j)
                    acc[i][j] += a[i] * bb[j];
        }
        __syncthreads();
    }

    // fused epilogue
    const float* Xb = x + (size_t)b * NN * NC;
#pragma unroll
    for (int i = 0; i < 8; ++i) {
        const int r = (i < 4) ? (ty * 4 + i) : (64 + ty * 4 + (i - 4));
        const int n = row0 + r;
        const float dg = g_deg[b * NN + n];
#pragma unroll
        for (int jh = 0; jh < 2; ++jh) {
            const int c = (jh == 0) ? (tx * 4) : (64 + tx * 4);
            const float4 zv = *(const float4*)(Zb + (size_t)n * NC + c);
            float zz[4] = {zv.x, zv.y, zv.z, zv.w};
            float o[4];
#pragma unroll
            for (int j = 0; j < 4; ++j)
                o[j] = alpha * (LRF * (dg * zz[j] - acc[i][jh * 4 + j]) - zz[j]);
            if (beta != 0.f) {
                const float4 xv = *(const float4*)(Xb + (size_t)n * NC + c);
                o[0] += beta * xv.x; o[1] += beta * xv.y;
                o[2] += beta * xv.z; o[3] += beta * xv.w;
            }
            float4 res; res.x = o[0]; res.y = o[1]; res.z = o[2]; res.w = o[3];
            *(float4*)(Zo + (size_t)n * NC + c) = res;
            if (copy_x)   // step1: Zb == x, stash slice 0
                *(float4*)(Zo0 + (size_t)n * NC + c) = zv;
        }
    }
}

// ---------------------------------------------------------------------------
// Final linear: out[b,n,o] = sum_{f<384} Zr[b,n,f] * W[o,f]
//   Zr rows = g_Z per-batch flat buffer at stride 384 (the .view trick).
// Same tile structure, K=384.
// ---------------------------------------------------------------------------
__global__ __launch_bounds__(256, 1)
void out_gemm_kernel(const float* __restrict__ W, float* __restrict__ out)
{
    const int b    = blockIdx.y;
    const int row0 = blockIdx.x * 128;
    const float* Zr = g_Z + (size_t)b * NKCH * NN * NC + (size_t)row0 * 384;

    __shared__ float As[8][128];
    __shared__ float Bs[8][128];   // Bs[k][o] = W[o, k0+k]

    const int tid  = threadIdx.x;
    const int tx   = tid & 15;
    const int ty   = tid >> 4;
    const int aRow = tid >> 1;
    const int aCol = (tid & 1) << 2;

    float acc[8][8];
#pragma unroll
    for (int i = 0; i < 8; ++i)
#pragma unroll
        for (int j = 0; j < 8; ++j) acc[i][j] = 0.f;

    float4 av = *(const float4*)(Zr + (size_t)aRow * 384 + aCol);
    float bv[4];
#pragma unroll
    for (int e = 0; e < 4; ++e) {
        const int lin = tid + e * 256;
        bv[e] = W[(size_t)(lin & 127) * 384 + (lin >> 7)];
    }

    for (int k0 = 0; k0 < 384; k0 += 8) {
        As[aCol + 0][aRow] = av.x;
        As[aCol + 1][aRow] = av.y;
        As[aCol + 2][aRow] = av.z;
        As[aCol + 3][aRow] = av.w;
#pragma unroll
        for (int e = 0; e < 4; ++e) {
            const int lin = tid + e * 256;
            Bs[lin >> 7][lin & 127] = bv[e];
        }
        __syncthreads();

        if (k0 + 8 < 384) {
            av = *(const float4*)(Zr + (size_t)aRow * 384 + (k0 + 8) + aCol);
#pragma unroll
            for (int e = 0; e < 4; ++e) {
                const int lin = tid + e * 256;
                bv[e] = W[(size_t)(lin & 127) * 384 + (k0 + 8) + (lin >> 7)];
            }
        }

#pragma unroll
        for (int kk = 0; kk < 8; ++kk) {
            float a[8], bb[8];
            *(float4*)&a[0]  = *(const float4*)&As[kk][ty * 4];
            *(float4*)&a[4]  = *(const float4*)&As[kk][64 + ty * 4];
            *(float4*)&bb[0] = *(const float4*)&Bs[kk][tx * 4];
            *(float4*)&bb[4] = *(const float4*)&Bs[kk][64 + tx * 4];
#pragma unroll
            for (int i = 0; i < 8; ++i)
#pragma unroll
                for (int j = 0; j < 8; ++j)
                    acc[i][j] += a[i] * bb[j];
        }
        __syncthreads();
    }

#pragma unroll
    for (int i = 0; i < 8; ++i) {
        const int r = (i < 4) ? (ty * 4 + i) : (64 + ty * 4 + (i - 4));
        const int n = row0 + r;
#pragma unroll
        for (int jh = 0; jh < 2; ++jh) {
            const int c = (jh == 0) ? (tx * 4) : (64 + tx * 4);
            float4 res;
            res.x = acc[i][jh * 4 + 0];
            res.y = acc[i][jh * 4 + 1];
            res.z = acc[i][jh * 4 + 2];
            res.w = acc[i][jh * 4 + 3];
            *(float4*)(out + ((size_t)b * NN + n) * NC + c) = res;
        }
    }
}

// ---------------------------------------------------------------------------
extern "C" void kernel_launch(void* const* d_in, const int* in_sizes, int n_in,
                              void* d_out, int out_size) {
    const float* x   = (const float*)d_in[0];   // [4,4096,128]
    const float* adj = (const float*)d_in[1];   // [4,4096,4096]
    const float* W   = (const float*)d_in[2];   // [128,384]
    float* out = (float*)d_out;                 // [4,4096,128] fp32

    (void)in_sizes; (void)n_in; (void)out_size;

    degree_partial_kernel<<<dim3(NN / 128, 16, NB), 128>>>(adj);
    degree_reduce_kernel<<<(NB * NN + 255) / 256, 256>>>();

    // step1: T1 = LR*(deg*x - adj@x) - x   (also copies x into slice 0)
    cheb_gemm_kernel<<<dim3(NN / 128, NB), 256>>>(adj, x, -1, 1, 1.f, 0.f, 1);
    // step2: T2 = 2*(LR*(deg*T1 - adj@T1) - T1) - x
    cheb_gemm_kernel<<<dim3(NN / 128, NB), 256>>>(adj, x, 1, 2, 2.f, -1.f, 0);

    // out = Zr @ W^T  with Zr = per-batch [4096 x 384] view of [x|T1|T2]
    out_gemm_kernel<<<dim3(NN / 128, NB), 256>>>(W, out);
}

// round 12
// speedup vs baseline: 2.2979x; 2.2979x over previous
#include <cuda_runtime.h>
#include <cstdint>

#define NB 4
#define NN 4096
#define NC 128
#define NKCH 3
#define LRF ((float)(2.0 / (2.0 + 1e-06)))

// ---------------------------------------------------------------------------
// Device scratch. g_Z is [b][k][n][c] contiguous, so the torch
// .view(B,N,-1) of stacked [B,K,N,C] == per-batch rows at stride 384.
// ---------------------------------------------------------------------------
__device__ float g_Z[(size_t)NB * NKCH * NN * NC];   // 24 MB
__device__ float g_degpart[16 * NB * NN];
__device__ float g_deg[NB * NN];

// ---------------------------------------------------------------------------
// degree[b,n] = sum_m adj[b,m,n] (deterministic 2-stage)
// ---------------------------------------------------------------------------
__global__ void degree_partial_kernel(const float* __restrict__ adj) {
    const int b   = blockIdx.z;
    const int col = blockIdx.x * 128 + threadIdx.x;
    const int r0  = blockIdx.y * 256;
    const float* A = adj + (size_t)b * NN * NN;
    float s = 0.f;
#pragma unroll 8
    for (int m = 0; m < 256; ++m)
        s += A[(size_t)(r0 + m) * NN + col];
    g_degpart[(size_t)blockIdx.y * NB * NN + b * NN + col] = s;
}

__global__ void degree_reduce_kernel() {
    int i = blockIdx.x * blockDim.x + threadIdx.x;
    if (i < NB * NN) {
        float s = 0.f;
#pragma unroll
        for (int r = 0; r < 16; ++r)
            s += g_degpart[(size_t)r * NB * NN + i];
        g_deg[i] = s;
    }
}

// ---------------------------------------------------------------------------
// Fused Chebyshev step via mma.sync tf32 (m16n8k8, fp32 accumulate):
//   acc = adj[rows] @ Zin
//   Zout[n,c] = alpha*( LRF*(deg[n]*Zin[n,c] - acc[n,c]) - Zin[n,c] ) + beta*x[n,c]
// step 0: Zin=x,      Zout=g_Z slice1, alpha=1, beta=0, also copy x -> slice0
// step 1: Zin=slice1, Zout=g_Z slice2, alpha=2, beta=-1
// ---------------------------------------------------------------------------
#define PITCH_A 36
#define PITCH_B 136
#define A_TILE_B (128 * PITCH_A * 4)            // 18432
#define STAGE_B  (A_TILE_B + 32 * PITCH_B * 4)  // 35840
#define NSTAGE 5
#define NCHUNK 128

__device__ __forceinline__ void mma_tf32_16x8x8(
    float* d, uint32_t a0, uint32_t a1, uint32_t a2, uint32_t a3,
    uint32_t b0, uint32_t b1)
{
    asm volatile(
        "mma.sync.aligned.m16n8k8.row.col.f32.tf32.tf32.f32 "
        "{%0,%1,%2,%3}, {%4,%5,%6,%7}, {%8,%9}, {%0,%1,%2,%3};"
        : "+f"(d[0]), "+f"(d[1]), "+f"(d[2]), "+f"(d[3])
        : "r"(a0), "r"(a1), "r"(a2), "r"(a3), "r"(b0), "r"(b1));
}

__global__ __launch_bounds__(128, 1)
void cheb_mma_kernel(const float* __restrict__ adj,
                     const float* __restrict__ x,
                     int step)
{
    extern __shared__ char dsm[];

    const int b    = blockIdx.y;
    const int row0 = blockIdx.x * 128;
    const int tid  = threadIdx.x;
    const int wid  = tid >> 5;
    const int lid  = tid & 31;
    const int g    = lid >> 2;      // groupID 0..7
    const int tig  = lid & 3;       // threadID_in_group 0..3
    const int mbase = (wid & 1) * 64;
    const int nbase = (wid >> 1) * 64;

    const float* Arow = adj + (size_t)b * NN * NN + (size_t)row0 * NN;
    const float* Xb   = x + (size_t)b * NN * NC;
    float* Zbase = g_Z + (size_t)b * NKCH * NN * NC;
    const float* Zin  = (step == 0) ? Xb : (Zbase + (size_t)1 * NN * NC);
    float*       Zout = (step == 0) ? (Zbase + (size_t)1 * NN * NC)
                                    : (Zbase + (size_t)2 * NN * NC);
    float* Z0 = Zbase;                       // slice 0 (x copy), step 0 only
    const float alpha = (step == 0) ? 1.f : 2.f;
    const float beta  = (step == 0) ? 0.f : -1.f;

    float acc[4][8][4];
#pragma unroll
    for (int mt = 0; mt < 4; ++mt)
#pragma unroll
        for (int nt = 0; nt < 8; ++nt)
#pragma unroll
            for (int q = 0; q < 4; ++q) acc[mt][nt][q] = 0.f;

    auto issue_chunk = [&](int chunk) {
        char* stg = dsm + (size_t)(chunk % NSTAGE) * STAGE_B;
        const int k0 = chunk * 32;
#pragma unroll
        for (int it = 0; it < 8; ++it) {
            const int idx = tid + it * 128;
            const int r = idx >> 3, q = idx & 7;
            char* dst = stg + (size_t)r * (PITCH_A * 4) + q * 16;
            const float* src = Arow + (size_t)r * NN + k0 + q * 4;
            uint32_t da;
            asm("{ .reg .u64 t; cvta.to.shared.u64 t, %1; cvt.u32.u64 %0, t; }"
                : "=r"(da) : "l"(dst));
            asm volatile("cp.async.cg.shared.global [%0], [%1], 16;"
                         :: "r"(da), "l"(src));
        }
#pragma unroll
        for (int it = 0; it < 8; ++it) {
            const int idx = tid + it * 128;
            const int r = idx >> 5, q = idx & 31;
            char* dst = stg + A_TILE_B + (size_t)r * (PITCH_B * 4) + q * 16;
            const float* src = Zin + (size_t)(k0 + r) * NC + q * 4;
            uint32_t db;
            asm("{ .reg .u64 t; cvta.to.shared.u64 t, %1; cvt.u32.u64 %0, t; }"
                : "=r"(db) : "l"(dst));
            asm volatile("cp.async.cg.shared.global [%0], [%1], 16;"
                         :: "r"(db), "l"(src));
        }
        asm volatile("cp.async.commit_group;" ::: "memory");
    };

    issue_chunk(0); issue_chunk(1); issue_chunk(2); issue_chunk(3);

    for (int c = 0; c < NCHUNK; ++c) {
        if (c < 125)       asm volatile("cp.async.wait_group 3;" ::: "memory");
        else if (c == 125) asm volatile("cp.async.wait_group 2;" ::: "memory");
        else if (c == 126) asm volatile("cp.async.wait_group 1;" ::: "memory");
        else               asm volatile("cp.async.wait_group 0;" ::: "memory");
        __syncthreads();

        if (c + 4 < NCHUNK) issue_chunk(c + 4);

        const float* As = (const float*)(dsm + (size_t)(c % NSTAGE) * STAGE_B);
        const float* Bs = (const float*)(dsm + (size_t)(c % NSTAGE) * STAGE_B + A_TILE_B);

#pragma unroll
        for (int ks = 0; ks < 4; ++ks) {
            const int kb = ks * 8;
            uint32_t a[4][4];
#pragma unroll
            for (int mt = 0; mt < 4; ++mt) {
                const int i0 = mbase + mt * 16 + g;
                a[mt][0] = __float_as_uint(As[(i0)     * PITCH_A + kb + tig]);
                a[mt][1] = __float_as_uint(As[(i0 + 8) * PITCH_A + kb + tig]);
                a[mt][2] = __float_as_uint(As[(i0)     * PITCH_A + kb + tig + 4]);
                a[mt][3] = __float_as_uint(As[(i0 + 8) * PITCH_A + kb + tig + 4]);
            }
#pragma unroll
            for (int nt = 0; nt < 8; ++nt) {
                const int j0 = nbase + nt * 8 + g;
                uint32_t b0 = __float_as_uint(Bs[(kb + tig)     * PITCH_B + j0]);
                uint32_t b1 = __float_as_uint(Bs[(kb + tig + 4) * PITCH_B + j0]);
#pragma unroll
                for (int mt = 0; mt < 4; ++mt)
                    mma_tf32_16x8x8(acc[mt][nt], a[mt][0], a[mt][1], a[mt][2], a[mt][3], b0, b1);
            }
        }
        __syncthreads();
    }

    // Fused epilogue (also stashes x into slice 0 on step 0)
#pragma unroll
    for (int mt = 0; mt < 4; ++mt) {
        const int r0 = row0 + mbase + mt * 16 + g;
        const int r1 = r0 + 8;
        const float dg0 = g_deg[b * NN + r0];
        const float dg1 = g_deg[b * NN + r1];
#pragma unroll
        for (int nt = 0; nt < 8; ++nt) {
            const int c0 = nbase + nt * 8 + 2 * tig;
            const float2 z0 = *(const float2*)(Zin + (size_t)r0 * NC + c0);
            const float2 z1 = *(const float2*)(Zin + (size_t)r1 * NC + c0);
            float2 o0, o1;
            o0.x = alpha * (LRF * (dg0 * z0.x - acc[mt][nt][0]) - z0.x);
            o0.y = alpha * (LRF * (dg0 * z0.y - acc[mt][nt][1]) - z0.y);
            o1.x = alpha * (LRF * (dg1 * z1.x - acc[mt][nt][2]) - z1.x);
            o1.y = alpha * (LRF * (dg1 * z1.y - acc[mt][nt][3]) - z1.y);
            if (beta != 0.f) {
                const float2 x0 = *(const float2*)(Xb + (size_t)r0 * NC + c0);
                const float2 x1 = *(const float2*)(Xb + (size_t)r1 * NC + c0);
                o0.x += beta * x0.x; o0.y += beta * x0.y;
                o1.x += beta * x1.x; o1.y += beta * x1.y;
            }
            *(float2*)(Zout + (size_t)r0 * NC + c0) = o0;
            *(float2*)(Zout + (size_t)r1 * NC + c0) = o1;
            if (step == 0) {
                *(float2*)(Z0 + (size_t)r0 * NC + c0) = z0;
                *(float2*)(Z0 + (size_t)r1 * NC + c0) = z1;
            }
        }
    }
}

// ---------------------------------------------------------------------------
// Final linear: out[b,n,o] = sum_{f<384} Zr[b,n,f] * W[o,f]
//   Zr = per-batch flat g_Z buffer read as rows of stride 384 (view trick).
// ---------------------------------------------------------------------------
__global__ __launch_bounds__(256, 1)
void out_gemm_kernel(const float* __restrict__ W, float* __restrict__ out)
{
    const int b    = blockIdx.y;
    const int row0 = blockIdx.x * 128;
    const float* Zr = g_Z + (size_t)b * NKCH * NN * NC + (size_t)row0 * 384;

    __shared__ float As[8][128];
    __shared__ float Bs[8][128];

    const int tid  = threadIdx.x;
    const int tx   = tid & 15;
    const int ty   = tid >> 4;
    const int aRow = tid >> 1;
    const int aCol = (tid & 1) << 2;

    float acc[8][8];
#pragma unroll
    for (int i = 0; i < 8; ++i)
#pragma unroll
        for (int j = 0; j < 8; ++j) acc[i][j] = 0.f;

    float4 av = *(const float4*)(Zr + (size_t)aRow * 384 + aCol);
    float bv[4];
#pragma unroll
    for (int e = 0; e < 4; ++e) {
        const int lin = tid + e * 256;
        bv[e] = W[(size_t)(lin & 127) * 384 + (lin >> 7)];
    }

    for (int k0 = 0; k0 < 384; k0 += 8) {
        As[aCol + 0][aRow] = av.x;
        As[aCol + 1][aRow] = av.y;
        As[aCol + 2][aRow] = av.z;
        As[aCol + 3][aRow] = av.w;
#pragma unroll
        for (int e = 0; e < 4; ++e) {
            const int lin = tid + e * 256;
            Bs[lin >> 7][lin & 127] = bv[e];
        }
        __syncthreads();

        if (k0 + 8 < 384) {
            av = *(const float4*)(Zr + (size_t)aRow * 384 + (k0 + 8) + aCol);
#pragma unroll
            for (int e = 0; e < 4; ++e) {
                const int lin = tid + e * 256;
                bv[e] = W[(size_t)(lin & 127) * 384 + (k0 + 8) + (lin >> 7)];
            }
        }

#pragma unroll
        for (int kk = 0; kk < 8; ++kk) {
            float a[8], bb[8];
            *(float4*)&a[0]  = *(const float4*)&As[kk][ty * 4];
            *(float4*)&a[4]  = *(const float4*)&As[kk][64 + ty * 4];
            *(float4*)&bb[0] = *(const float4*)&Bs[kk][tx * 4];
            *(float4*)&bb[4] = *(const float4*)&Bs[kk][64 + tx * 4];
#pragma unroll
            for (int i = 0; i < 8; ++i)
#pragma unroll
                for (int j = 0; j < 8; ++j)
                    acc[i][j] += a[i] * bb[j];
        }
        __syncthreads();
    }

#pragma unroll
    for (int i = 0; i < 8; ++i) {
        const int r = (i < 4) ? (ty * 4 + i) : (64 + ty * 4 + (i - 4));
        const int n = row0 + r;
#pragma unroll
        for (int jh = 0; jh < 2; ++jh) {
            const int c = (jh == 0) ? (tx * 4) : (64 + tx * 4);
            float4 res;
            res.x = acc[i][jh * 4 + 0];
            res.y = acc[i][jh * 4 + 1];
            res.z = acc[i][jh * 4 + 2];
            res.w = acc[i][jh * 4 + 3];
            *(float4*)(out + ((size_t)b * NN + n) * NC + c) = res;
        }
    }
}

// ---------------------------------------------------------------------------
extern "C" void kernel_launch(void* const* d_in, const int* in_sizes, int n_in,
                              void* d_out, int out_size) {
    const float* x   = (const float*)d_in[0];   // [4,4096,128]
    const float* adj = (const float*)d_in[1];   // [4,4096,4096]
    const float* W   = (const float*)d_in[2];   // [128,384]
    float* out = (float*)d_out;

    (void)in_sizes; (void)n_in; (void)out_size;

    const int SMEM_CHEB = NSTAGE * STAGE_B;     // 179200 B
    cudaFuncSetAttribute(cheb_mma_kernel,
                         cudaFuncAttributeMaxDynamicSharedMemorySize, SMEM_CHEB);

    degree_partial_kernel<<<dim3(NN / 128, 16, NB), 128>>>(adj);
    degree_reduce_kernel<<<(NB * NN + 255) / 256, 256>>>();

    // T1 = LR*(deg*x - adj@x) - x           (also stashes x into slice 0)
    cheb_mma_kernel<<<dim3(NN / 128, NB), 128, SMEM_CHEB>>>(adj, x, 0);
    // T2 = 2*(LR*(deg*T1 - adj@T1) - T1) - x
    cheb_mma_kernel<<<dim3(NN / 128, NB), 128, SMEM_CHEB>>>(adj, x, 1);

    out_gemm_kernel<<<dim3(NN / 128, NB), 256>>>(W, out);
}